// round 8
// baseline (speedup 1.0000x reference)
#include <cuda_runtime.h>
#include <cuda_fp16.h>
#include <cstdint>

#define SEQ 512
#define BATCH 64
#define HID 1024
#define G4 4096
#define BH (BATCH*HID)
#define BG (BATCH*G4)
#define YSZ (SEQ*BH)
#define HOFF YSZ
#define COFF (YSZ+2*BH)
#define NCTA 128

__device__ __align__(16) float  g_gi[SEQ*BG];     // input projections (fp32)
__device__ __align__(16) __half g_xh[SEQ*BH];     // x in fp16
__device__ __align__(16) __half g_h16[SEQ*BH];    // h stream fp16 (per layer)
__device__ __align__(16) __half g_wh[2*G4*HID];   // W_ih fp16, both layers
__device__ volatile int g_flags[NCTA*32];         // barrier arrival flags
__device__ volatile int g_gen;                    // barrier release word

// ---------------- helpers ---------------------------------------------------
__device__ __forceinline__ uint32_t smem_u32(const void* p) {
    uint32_t a;
    asm("{ .reg .u64 t; cvta.to.shared.u64 t, %1; cvt.u32.u64 %0, t; }"
        : "=r"(a) : "l"(p));
    return a;
}
#define SW128(x) ((x) ^ (((x) >> 3) & 0x70))

__device__ __forceinline__ void cp_async16(uint32_t dst, const void* src) {
    asm volatile("cp.async.cg.shared.global [%0], [%1], 16;" :: "r"(dst), "l"(src));
}
__device__ __forceinline__ void cp_commit() {
    asm volatile("cp.async.commit_group;");
}
template <int N> __device__ __forceinline__ void cp_wait() {
    asm volatile("cp.async.wait_group %0;" :: "n"(N));
}
__device__ __forceinline__ void cp_wait_n(int n) {
    switch (n) {
        case 0: cp_wait<0>(); break;  case 1: cp_wait<1>(); break;
        case 2: cp_wait<2>(); break;  case 3: cp_wait<3>(); break;
        case 4: cp_wait<4>(); break;  case 5: cp_wait<5>(); break;
        case 6: cp_wait<6>(); break;  default: cp_wait<7>(); break;
    }
}
__device__ __forceinline__ void sts128(uint32_t a, uint32_t x, uint32_t y,
                                       uint32_t z, uint32_t w) {
    asm volatile("st.shared.v4.b32 [%0], {%1,%2,%3,%4};"
                 :: "r"(a), "r"(x), "r"(y), "r"(z), "r"(w) : "memory");
}
__device__ __forceinline__ void ldm4(uint32_t* r, uint32_t a) {
    asm volatile("ldmatrix.sync.aligned.m8n8.x4.shared.b16 {%0,%1,%2,%3}, [%4];"
                 : "=r"(r[0]), "=r"(r[1]), "=r"(r[2]), "=r"(r[3]) : "r"(a));
}
__device__ __forceinline__ void ldm2(uint32_t* r, uint32_t a) {
    asm volatile("ldmatrix.sync.aligned.m8n8.x2.shared.b16 {%0,%1}, [%2];"
                 : "=r"(r[0]), "=r"(r[1]) : "r"(a));
}
__device__ __forceinline__ void mma16816(float* c, const uint32_t* a,
                                         const uint32_t* b) {
    asm volatile(
        "mma.sync.aligned.m16n8k16.row.col.f32.f16.f16.f32 "
        "{%0,%1,%2,%3}, {%4,%5,%6,%7}, {%8,%9}, {%0,%1,%2,%3};"
        : "+f"(c[0]), "+f"(c[1]), "+f"(c[2]), "+f"(c[3])
        : "r"(a[0]), "r"(a[1]), "r"(a[2]), "r"(a[3]), "r"(b[0]), "r"(b[1]));
}
__device__ __forceinline__ float sigm(float x)   { return 1.f / (1.f + __expf(-x)); }
__device__ __forceinline__ float tanh_f(float x) { return 1.f - 2.f / (__expf(2.f*x) + 1.f); }
__device__ __forceinline__ uint32_t h2u(__half2 h) { return *(uint32_t*)&h; }

// ---------------------------------------------------------------------------
__global__ void f2h_kernel(const float* __restrict__ in, __half* __restrict__ o,
                           int n8) {
    int i = blockIdx.x * 256 + threadIdx.x;
    if (i < n8) {
        float4 a = ((const float4*)in)[2*i];
        float4 b = ((const float4*)in)[2*i+1];
        uint4 v;
        v.x = h2u(__floats2half2_rn(a.x, a.y));
        v.y = h2u(__floats2half2_rn(a.z, a.w));
        v.z = h2u(__floats2half2_rn(b.x, b.y));
        v.w = h2u(__floats2half2_rn(b.z, b.w));
        ((uint4*)o)[i] = v;
    }
}

// ---------------------------------------------------------------------------
// gi = A(fp16)@B(fp16)^T + b1 + b2.  M=32768,N=4096,K=1024.
// CTA 128x128, 8 warps (2m x 4n), warptile 64x32, double-buffered cp.async.
#define GH_SMEM (1024 + 65536)
__global__ __launch_bounds__(256, 2) void gemm_h(
    const __half* __restrict__ A, const __half* __restrict__ B,
    const float* __restrict__ b1, const float* __restrict__ b2,
    float* __restrict__ C)
{
    extern __shared__ char sm_[];
    const uint32_t base = (smem_u32(sm_) + 1023) & ~1023u;
    const int tid = threadIdx.x, wid = tid >> 5, lane = tid & 31;
    const int nb = blockIdx.x * 128, mb = blockIdx.y * 128;
    const int wm = wid >> 2, wn = wid & 3;

    const int lrow = tid >> 1;
    const int ls0  = (tid & 1) * 4;
    const char* asrc0 = (const char*)(A + (size_t)(mb + lrow) * 1024);
    const char* bsrc0 = (const char*)(B + (size_t)(nb + lrow) * 1024);

    float acc[4][4][4];
#pragma unroll
    for (int i = 0; i < 4; i++)
#pragma unroll
        for (int j = 0; j < 4; j++)
#pragma unroll
            for (int q = 0; q < 4; q++) acc[i][j][q] = 0.f;

    const int lr = lane & 7, lg = lane >> 3;
    const int arow = lr + ((lg & 1) << 3), aksel = lg >> 1;
    const int brow = lr + ((lg >> 1) << 3), bksel = lg & 1;

#pragma unroll
    for (int i = 0; i < 4; i++) {
        int s = ls0 + i;
        cp_async16(base + SW128(lrow * 128 + s * 16), asrc0 + s * 16);
        cp_async16(base + 16384 + SW128(lrow * 128 + s * 16), bsrc0 + s * 16);
    }
    cp_commit();

    for (int c = 0; c < 16; c++) {
        if (c < 15) {
            uint32_t ab = base + ((c + 1) & 1) * 32768;
#pragma unroll
            for (int i = 0; i < 4; i++) {
                int s = ls0 + i;
                cp_async16(ab + SW128(lrow * 128 + s * 16),
                           asrc0 + (c + 1) * 128 + s * 16);
                cp_async16(ab + 16384 + SW128(lrow * 128 + s * 16),
                           bsrc0 + (c + 1) * 128 + s * 16);
            }
            cp_commit();
            cp_wait<1>();
        } else {
            cp_wait<0>();
        }
        __syncthreads();
        uint32_t ab = base + (c & 1) * 32768;
        uint32_t bb = ab + 16384;
#pragma unroll
        for (int ks = 0; ks < 4; ks++) {
            uint32_t afr[4][4], bfr[2][4];
#pragma unroll
            for (int mf = 0; mf < 4; mf++)
                ldm4(afr[mf], ab + SW128((wm * 64 + mf * 16 + arow) * 128
                                         + (ks * 2 + aksel) * 16));
#pragma unroll
            for (int bh = 0; bh < 2; bh++)
                ldm4(bfr[bh], bb + SW128((wn * 32 + bh * 16 + brow) * 128
                                         + (ks * 2 + bksel) * 16));
#pragma unroll
            for (int mf = 0; mf < 4; mf++)
#pragma unroll
                for (int nf = 0; nf < 4; nf++)
                    mma16816(acc[mf][nf], afr[mf], &bfr[nf >> 1][(nf & 1) * 2]);
        }
        __syncthreads();
    }

#pragma unroll
    for (int mf = 0; mf < 4; mf++) {
#pragma unroll
        for (int nf = 0; nf < 4; nf++) {
            int m = mb + wm * 64 + mf * 16 + (lane >> 2);
            int n = nb + wn * 32 + nf * 8 + 2 * (lane & 3);
            float bs0 = b1[n] + b2[n], bs1 = b1[n + 1] + b2[n + 1];
            float* cp0 = C + (size_t)m * 4096 + n;
            float* cp1 = cp0 + 8 * 4096;
            *(float2*)cp0 = make_float2(acc[mf][nf][0] + bs0, acc[mf][nf][1] + bs1);
            *(float2*)cp1 = make_float2(acc[mf][nf][2] + bs0, acc[mf][nf][3] + bs1);
        }
    }
}

// ---------------------------------------------------------------------------
// Distributed-flag grid barrier: no serialized atomics.
__device__ __forceinline__ void grid_sync2(int sv, int jb) {
    __syncthreads();
    if (threadIdx.x == 0) {
        __threadfence();
        g_flags[jb * 32] = sv;
    }
    if (jb == 0) {
        if (threadIdx.x < NCTA) {
            while ((int)(g_flags[threadIdx.x * 32] - sv) < 0) { }
        }
        __syncthreads();
        if (threadIdx.x == 0) {
            __threadfence();
            g_gen = sv;
        }
    } else {
        if (threadIdx.x == 0) {
            while ((int)(g_gen - sv) < 0) __nanosleep(16);
            __threadfence();
        }
    }
    __syncthreads();
}

// ---------------------------------------------------------------------------
// Persistent recurrence. CTA jb owns 32 gate cols lc=g*8+jl -> row g*1024+jb*8+jl.
// SMEM: W fp16 16 chunks [32lc x 64k] (64KB) | A fp16 16 chunks [64b x 64k]
// (128KB) | Gs fp32 [32][68].
#define R_SMEM (1024 + 65536 + 131072 + 8704)
__global__ __launch_bounds__(256) void lstm_h(
    const float* __restrict__ Whh, const float* __restrict__ gi,
    __half* __restrict__ h16, float* __restrict__ yout,
    float* __restrict__ out, int layer, int full)
{
    extern __shared__ char sm_[];
    const uint32_t base = (smem_u32(sm_) + 1023) & ~1023u;
    const uint32_t Wb = base, Ab = base + 65536, GsB = base + 196608;
    float* Gs = (float*)(sm_ + (GsB - smem_u32(sm_)));
    const int tid = threadIdx.x, wid = tid >> 5, lane = tid & 31;
    const int jb = blockIdx.x;

    // W_hh slice -> fp16 SMEM
#pragma unroll 2
    for (int it = 0; it < 16; it++) {
        int idx = tid + it * 256;
        int lc = idx >> 7;
        int k8 = (idx & 127) * 8;
        int grow = ((lc >> 3) << 10) + jb * 8 + (lc & 7);
        const float* wp = Whh + (size_t)grow * 1024 + k8;
        float4 u = *(const float4*)wp;
        float4 v = *(const float4*)(wp + 4);
        sts128(Wb + (k8 >> 6) * 4096 + SW128(lc * 128 + (k8 & 63) * 2),
               h2u(__floats2half2_rn(u.x, u.y)), h2u(__floats2half2_rn(u.z, u.w)),
               h2u(__floats2half2_rn(v.x, v.y)), h2u(__floats2half2_rn(v.z, v.w)));
    }
    int sv0 = g_gen;                          // stable between launches
    __syncthreads();

    const int wm = wid >> 2, wn = wid & 3;
    const int m0 = wm * 32, n0 = wn * 8;
    const int lr = lane & 7, lg = lane >> 3;
    const int arow = lr + ((lg & 1) << 3), aksel = lg >> 1;
    const int bnr = lane & 7, bksel = (lane >> 3) & 1;
    const int ldrow = tid >> 3, lds = tid & 7;

    // cell-update mapping: thread -> batch cb, jl pair cj0
    const int cb = tid >> 2;
    const int cj0 = 2 * (tid & 3);
    float creg2[2] = {0.f, 0.f};

    for (int t = 0; t < SEQ; t++) {
        // ---- gi prefetch (hidden behind GEMM phase) ----
        const float* gp = gi + (size_t)t * BG + (size_t)cb * 4096 + jb * 8 + cj0;
        float2 ggv[4];
#pragma unroll
        for (int g = 0; g < 4; g++) ggv[g] = *(const float2*)(gp + (g << 10));

        if (t > 0) {
            const char* hp = (const char*)(h16 + (size_t)(t - 1) * BH);
            // issue all h loads: 8 commit-groups of 2 chunks
#pragma unroll
            for (int gch = 0; gch < 8; gch++) {
#pragma unroll
                for (int cc = 0; cc < 2; cc++) {
                    int c = gch * 2 + cc;
                    cp_async16(Ab + c * 8192 + SW128(ldrow * 128 + lds * 16),
                               hp + ldrow * 2048 + c * 128 + lds * 16);
                    cp_async16(Ab + c * 8192 + SW128((ldrow + 32) * 128 + lds * 16),
                               hp + (ldrow + 32) * 2048 + c * 128 + lds * 16);
                }
                cp_commit();
            }
            float acc[2][4];
#pragma unroll
            for (int f = 0; f < 2; f++)
#pragma unroll
                for (int q = 0; q < 4; q++) acc[f][q] = 0.f;

#pragma unroll
            for (int gch = 0; gch < 8; gch++) {
                cp_wait_n(7 - gch);
                __syncthreads();
#pragma unroll
                for (int cc = 0; cc < 2; cc++) {
                    int c = gch * 2 + cc;
#pragma unroll
                    for (int ks = 0; ks < 4; ks++) {
                        uint32_t afr[2][4], bfr[2];
                        ldm4(afr[0], Ab + c * 8192
                             + SW128((m0 + arow) * 128 + (ks * 2 + aksel) * 16));
                        ldm4(afr[1], Ab + c * 8192
                             + SW128((m0 + 16 + arow) * 128 + (ks * 2 + aksel) * 16));
                        ldm2(bfr, Wb + c * 4096
                             + SW128((n0 + bnr) * 128 + (ks * 2 + bksel) * 16));
                        mma16816(acc[0], afr[0], bfr);
                        mma16816(acc[1], afr[1], bfr);
                    }
                }
            }
            // exchange gates via SMEM: Gs[col][b]
#pragma unroll
            for (int f = 0; f < 2; f++) {
                int b = m0 + f * 16 + (lane >> 2);
                int col = n0 + 2 * (lane & 3);
                Gs[col * 68 + b]           = acc[f][0];
                Gs[(col + 1) * 68 + b]     = acc[f][1];
                Gs[col * 68 + b + 8]       = acc[f][2];
                Gs[(col + 1) * 68 + b + 8] = acc[f][3];
            }
            __syncthreads();
        }

        // ---- cell update: all 256 threads, 2 cells each ----
        float hv2[2];
#pragma unroll
        for (int e = 0; e < 2; e++) {
            int jl = cj0 + e;
            float i_g = (e ? ggv[0].y : ggv[0].x);
            float f_g = (e ? ggv[1].y : ggv[1].x);
            float g_g = (e ? ggv[2].y : ggv[2].x);
            float o_g = (e ? ggv[3].y : ggv[3].x);
            if (t > 0) {
                i_g += Gs[(0 * 8 + jl) * 68 + cb];
                f_g += Gs[(1 * 8 + jl) * 68 + cb];
                g_g += Gs[(2 * 8 + jl) * 68 + cb];
                o_g += Gs[(3 * 8 + jl) * 68 + cb];
            }
            float cn = sigm(f_g) * creg2[e] + sigm(i_g) * tanh_f(g_g);
            creg2[e] = cn;
            hv2[e] = sigm(o_g) * tanh_f(cn);
        }
        size_t off = (size_t)t * BH + (size_t)cb * 1024 + jb * 8 + cj0;
        *(uint32_t*)(h16 + off) = h2u(__floats2half2_rn(hv2[0], hv2[1]));
        if (yout) *(float2*)(yout + off) = make_float2(hv2[0], hv2[1]);
        if (t == SEQ - 1 && full) {
            size_t tail = (size_t)layer * BH + (size_t)cb * 1024 + jb * 8 + cj0;
            *(float2*)(out + HOFF + tail) = make_float2(hv2[0], hv2[1]);
            *(float2*)(out + COFF + tail) = make_float2(creg2[0], creg2[1]);
        }
        if (t < SEQ - 1) grid_sync2(sv0 + t + 1, jb);
    }
}

// ---------------------------------------------------------------------------
extern "C" void kernel_launch(void* const* d_in, const int* in_sizes, int n_in,
                              void* d_out, int out_size)
{
    const float* x    = (const float*)d_in[0];
    const float* wih0 = (const float*)d_in[1];
    const float* whh0 = (const float*)d_in[2];
    const float* bih0 = (const float*)d_in[3];
    const float* bhh0 = (const float*)d_in[4];
    const float* wih1 = (const float*)d_in[5];
    const float* whh1 = (const float*)d_in[6];
    const float* bih1 = (const float*)d_in[7];
    const float* bhh1 = (const float*)d_in[8];
    float* out = (float*)d_out;

    float *gi; __half *xh, *h16, *wh;
    cudaGetSymbolAddress((void**)&gi,  g_gi);
    cudaGetSymbolAddress((void**)&xh,  g_xh);
    cudaGetSymbolAddress((void**)&h16, g_h16);
    cudaGetSymbolAddress((void**)&wh,  g_wh);

    cudaFuncSetAttribute(gemm_h, cudaFuncAttributeMaxDynamicSharedMemorySize, GH_SMEM);
    cudaFuncSetAttribute(lstm_h, cudaFuncAttributeMaxDynamicSharedMemorySize, R_SMEM);

    const int full = (out_size >= (int)(YSZ + 4 * BH)) ? 1 : 0;
    dim3 gg(32, 256);
    const int WN8 = G4 * HID / 8;

    // upfront conversions (x, both W_ih)
    f2h_kernel<<<(SEQ * BH / 8 + 255) / 256, 256>>>(x, xh, SEQ * BH / 8);
    f2h_kernel<<<(WN8 + 255) / 256, 256>>>(wih0, wh, WN8);
    f2h_kernel<<<(WN8 + 255) / 256, 256>>>(wih1, wh + (size_t)G4 * HID, WN8);

    // Layer 0
    gemm_h<<<gg, 256, GH_SMEM>>>(xh, wh, bih0, bhh0, gi);
    lstm_h<<<NCTA, 256, R_SMEM>>>(whh0, gi, h16, (float*)0, out, 0, full);
    // Layer 1 (A operand = h16 written by layer 0)
    gemm_h<<<gg, 256, GH_SMEM>>>(h16, wh + (size_t)G4 * HID, bih1, bhh1, gi);
    lstm_h<<<NCTA, 256, R_SMEM>>>(whh1, gi, h16, out, out, 1, full);
}

// round 9
// speedup vs baseline: 1.5854x; 1.5854x over previous
#include <cuda_runtime.h>
#include <cuda_fp16.h>
#include <cstdint>

#define SEQ 512
#define BATCH 64
#define HID 1024
#define G4 4096
#define BH (BATCH*HID)
#define BG (BATCH*G4)
#define YSZ (SEQ*BH)
#define HOFF YSZ
#define COFF (YSZ+2*BH)
#define NCTA 128

__device__ __align__(16) float  g_gi[SEQ*BG];     // input projections (fp32)
__device__ __align__(16) __half g_xh[SEQ*BH];     // x in fp16
__device__ __align__(16) __half g_h16[SEQ*BH];    // h stream fp16 (per layer)
__device__ __align__(16) __half g_wh[2*G4*HID];   // W_ih fp16, both layers
__device__ int g_flags[NCTA*32];                  // per-CTA progress flags

// ---------------- helpers ---------------------------------------------------
__device__ __forceinline__ uint32_t smem_u32(const void* p) {
    uint32_t a;
    asm("{ .reg .u64 t; cvta.to.shared.u64 t, %1; cvt.u32.u64 %0, t; }"
        : "=r"(a) : "l"(p));
    return a;
}
#define SW128(x) ((x) ^ (((x) >> 3) & 0x70))

__device__ __forceinline__ void cp_async16(uint32_t dst, const void* src) {
    asm volatile("cp.async.cg.shared.global [%0], [%1], 16;" :: "r"(dst), "l"(src));
}
__device__ __forceinline__ void cp_commit() {
    asm volatile("cp.async.commit_group;");
}
template <int N> __device__ __forceinline__ void cp_wait() {
    asm volatile("cp.async.wait_group %0;" :: "n"(N));
}
__device__ __forceinline__ void sts128(uint32_t a, uint32_t x, uint32_t y,
                                       uint32_t z, uint32_t w) {
    asm volatile("st.shared.v4.b32 [%0], {%1,%2,%3,%4};"
                 :: "r"(a), "r"(x), "r"(y), "r"(z), "r"(w) : "memory");
}
__device__ __forceinline__ void ldm4(uint32_t* r, uint32_t a) {
    asm volatile("ldmatrix.sync.aligned.m8n8.x4.shared.b16 {%0,%1,%2,%3}, [%4];"
                 : "=r"(r[0]), "=r"(r[1]), "=r"(r[2]), "=r"(r[3]) : "r"(a));
}
__device__ __forceinline__ void ldm2(uint32_t* r, uint32_t a) {
    asm volatile("ldmatrix.sync.aligned.m8n8.x2.shared.b16 {%0,%1}, [%2];"
                 : "=r"(r[0]), "=r"(r[1]) : "r"(a));
}
__device__ __forceinline__ void mma16816(float* c, const uint32_t* a,
                                         const uint32_t* b) {
    asm volatile(
        "mma.sync.aligned.m16n8k16.row.col.f32.f16.f16.f32 "
        "{%0,%1,%2,%3}, {%4,%5,%6,%7}, {%8,%9}, {%0,%1,%2,%3};"
        : "+f"(c[0]), "+f"(c[1]), "+f"(c[2]), "+f"(c[3])
        : "r"(a[0]), "r"(a[1]), "r"(a[2]), "r"(a[3]), "r"(b[0]), "r"(b[1]));
}
__device__ __forceinline__ float sigm(float x)   { return 1.f / (1.f + __expf(-x)); }
__device__ __forceinline__ float tanh_f(float x) { return 1.f - 2.f / (__expf(2.f*x) + 1.f); }
__device__ __forceinline__ uint32_t h2u(__half2 h) { return *(uint32_t*)&h; }

// ---------------------------------------------------------------------------
__global__ void reset_flags_kernel() {
    if (threadIdx.x < NCTA) g_flags[threadIdx.x * 32] = 0;
}

__global__ void f2h_kernel(const float* __restrict__ in, __half* __restrict__ o,
                           int n8) {
    int i = blockIdx.x * 256 + threadIdx.x;
    if (i < n8) {
        float4 a = ((const float4*)in)[2*i];
        float4 b = ((const float4*)in)[2*i+1];
        uint4 v;
        v.x = h2u(__floats2half2_rn(a.x, a.y));
        v.y = h2u(__floats2half2_rn(a.z, a.w));
        v.z = h2u(__floats2half2_rn(b.x, b.y));
        v.w = h2u(__floats2half2_rn(b.z, b.w));
        ((uint4*)o)[i] = v;
    }
}

// ---------------------------------------------------------------------------
// gi = A(fp16)@B(fp16)^T + b1 + b2.  M=32768,N=4096,K=1024. (unchanged, works)
#define GH_SMEM (1024 + 65536)
__global__ __launch_bounds__(256, 2) void gemm_h(
    const __half* __restrict__ A, const __half* __restrict__ B,
    const float* __restrict__ b1, const float* __restrict__ b2,
    float* __restrict__ C)
{
    extern __shared__ char sm_[];
    const uint32_t base = (smem_u32(sm_) + 1023) & ~1023u;
    const int tid = threadIdx.x, wid = tid >> 5, lane = tid & 31;
    const int nb = blockIdx.x * 128, mb = blockIdx.y * 128;
    const int wm = wid >> 2, wn = wid & 3;

    const int lrow = tid >> 1;
    const int ls0  = (tid & 1) * 4;
    const char* asrc0 = (const char*)(A + (size_t)(mb + lrow) * 1024);
    const char* bsrc0 = (const char*)(B + (size_t)(nb + lrow) * 1024);

    float acc[4][4][4];
#pragma unroll
    for (int i = 0; i < 4; i++)
#pragma unroll
        for (int j = 0; j < 4; j++)
#pragma unroll
            for (int q = 0; q < 4; q++) acc[i][j][q] = 0.f;

    const int lr = lane & 7, lg = lane >> 3;
    const int arow = lr + ((lg & 1) << 3), aksel = lg >> 1;
    const int brow = lr + ((lg >> 1) << 3), bksel = lg & 1;

#pragma unroll
    for (int i = 0; i < 4; i++) {
        int s = ls0 + i;
        cp_async16(base + SW128(lrow * 128 + s * 16), asrc0 + s * 16);
        cp_async16(base + 16384 + SW128(lrow * 128 + s * 16), bsrc0 + s * 16);
    }
    cp_commit();

    for (int c = 0; c < 16; c++) {
        if (c < 15) {
            uint32_t ab = base + ((c + 1) & 1) * 32768;
#pragma unroll
            for (int i = 0; i < 4; i++) {
                int s = ls0 + i;
                cp_async16(ab + SW128(lrow * 128 + s * 16),
                           asrc0 + (c + 1) * 128 + s * 16);
                cp_async16(ab + 16384 + SW128(lrow * 128 + s * 16),
                           bsrc0 + (c + 1) * 128 + s * 16);
            }
            cp_commit();
            cp_wait<1>();
        } else {
            cp_wait<0>();
        }
        __syncthreads();
        uint32_t ab = base + (c & 1) * 32768;
        uint32_t bb = ab + 16384;
#pragma unroll
        for (int ks = 0; ks < 4; ks++) {
            uint32_t afr[4][4], bfr[2][4];
#pragma unroll
            for (int mf = 0; mf < 4; mf++)
                ldm4(afr[mf], ab + SW128((wm * 64 + mf * 16 + arow) * 128
                                         + (ks * 2 + aksel) * 16));
#pragma unroll
            for (int bh = 0; bh < 2; bh++)
                ldm4(bfr[bh], bb + SW128((wn * 32 + bh * 16 + brow) * 128
                                         + (ks * 2 + bksel) * 16));
#pragma unroll
            for (int mf = 0; mf < 4; mf++)
#pragma unroll
                for (int nf = 0; nf < 4; nf++)
                    mma16816(acc[mf][nf], afr[mf], &bfr[nf >> 1][(nf & 1) * 2]);
        }
        __syncthreads();
    }

#pragma unroll
    for (int mf = 0; mf < 4; mf++) {
#pragma unroll
        for (int nf = 0; nf < 4; nf++) {
            int m = mb + wm * 64 + mf * 16 + (lane >> 2);
            int n = nb + wn * 32 + nf * 8 + 2 * (lane & 3);
            float bs0 = b1[n] + b2[n], bs1 = b1[n + 1] + b2[n + 1];
            float* cp0 = C + (size_t)m * 4096 + n;
            float* cp1 = cp0 + 8 * 4096;
            *(float2*)cp0 = make_float2(acc[mf][nf][0] + bs0, acc[mf][nf][1] + bs1);
            *(float2*)cp1 = make_float2(acc[mf][nf][2] + bs0, acc[mf][nf][3] + bs1);
        }
    }
}

// ---------------------------------------------------------------------------
// Dataflow recurrence: NO global barrier. 128 CTAs = 64 col-groups x 2 batch
// halves. CTA (cg,bs): M=32 batches, N=64 gate cols {g*1024+cg*16+jl}, K=1024.
// Per-step h buffers (g_h16[t]) -> no WAR hazard; producers publish flags[jb]
// = t+1 (release) after storing h(t); consumers acquire-poll only the flags
// feeding each K-group and pipeline loads/MMA against the poll.
// SMEM: W 128KB (16 chunks x 64 cols x 64k) | A 16KB x 4 groups | Gs 64x33 f32.
#define R_SMEM (1024 + 131072 + 65536 + 8448)
__global__ __launch_bounds__(256) void lstm_df(
    const float* __restrict__ Whh, const float* __restrict__ gi,
    __half* __restrict__ h16, float* __restrict__ yout,
    float* __restrict__ out, int layer, int full)
{
    extern __shared__ char sm_[];
    const uint32_t base = (smem_u32(sm_) + 1023) & ~1023u;
    const uint32_t Wb = base, Ab = base + 131072, GsB = base + 196608;
    float* Gs = (float*)(sm_ + (GsB - smem_u32(sm_)));
    const int tid = threadIdx.x, wid = tid >> 5, lane = tid & 31;
    const int jb = blockIdx.x;
    const int cg = jb >> 1;            // col-group 0..63
    const int bs = jb & 1;             // batch half 0..1

    // ---- W_hh slice -> fp16 SMEM: 64 cols x 1024 k, 16 chunks of 64k ----
#pragma unroll 2
    for (int it = 0; it < 32; it++) {
        int idx = tid + it * 256;              // 0..8191
        int lc = idx >> 7;                     // 0..63 local col
        int k8 = (idx & 127) * 8;              // 0..1016
        int grow = ((lc >> 4) << 10) + cg * 16 + (lc & 15);
        const float* wp = Whh + (size_t)grow * 1024 + k8;
        float4 u = *(const float4*)wp;
        float4 v = *(const float4*)(wp + 4);
        sts128(Wb + (k8 >> 6) * 8192 + SW128(lc * 128 + (k8 & 63) * 2),
               h2u(__floats2half2_rn(u.x, u.y)), h2u(__floats2half2_rn(u.z, u.w)),
               h2u(__floats2half2_rn(v.x, v.y)), h2u(__floats2half2_rn(v.z, v.w)));
    }
    __syncthreads();

    const int wn = wid;                        // 0..7: 8 cols each
    const int n0 = wn * 8;
    const int lr = lane & 7, lg = lane >> 3;
    const int arow = lr + ((lg & 1) << 3), aksel = lg >> 1;
    const int bnr = lane & 7, bksel = (lane >> 3) & 1;
    const int srow = tid >> 3, sseg = tid & 7; // cp.async: 32 rows x 8 segs

    // cell mapping: thread -> (batch local bl, jl pair jl0)
    const int bl = tid >> 3;                   // 0..31
    const int jl0 = (tid & 7) * 2;             // 0..14
    float creg2[2] = {0.f, 0.f};

    for (int t = 0; t < SEQ; t++) {
        // gi prefetch (overlaps polls/loads)
        const float* gp = gi + (size_t)t * BG
                        + (size_t)(bs * 32 + bl) * 4096 + cg * 16 + jl0;
        float2 ggv[4];
#pragma unroll
        for (int g = 0; g < 4; g++) ggv[g] = *(const float2*)(gp + (g << 10));

        if (t > 0) {
            const char* hp = (const char*)(h16 + (size_t)(t - 1) * BH);
            // poll+issue groups 0,1 ; then pipelined compute
#pragma unroll
            for (int g = 0; g < 2; g++) {
                if (tid < 16) {
                    const int* fp = (const int*)&g_flags[((g * 16 + tid) * 2 + bs) * 32];
                    int v;
                    do {
                        asm volatile("ld.acquire.gpu.global.b32 %0, [%1];"
                                     : "=r"(v) : "l"(fp));
                    } while (v < t);
                }
                __syncthreads();
#pragma unroll
                for (int cc = 0; cc < 4; cc++) {
                    int c = g * 4 + cc;
                    cp_async16(Ab + c * 4096 + SW128(srow * 128 + sseg * 16),
                               hp + (size_t)(bs * 32 + srow) * 2048 + c * 128 + sseg * 16);
                }
                cp_commit();
            }
            float acc[2][4];
#pragma unroll
            for (int f = 0; f < 2; f++)
#pragma unroll
                for (int q = 0; q < 4; q++) acc[f][q] = 0.f;

#pragma unroll
            for (int g = 0; g < 4; g++) {
                if (g < 3) cp_wait<1>(); else cp_wait<0>();
                __syncthreads();
#pragma unroll
                for (int cc = 0; cc < 4; cc++) {
                    int c = g * 4 + cc;
                    uint32_t wbase = Wb + c * 8192, abase = Ab + c * 4096;
#pragma unroll
                    for (int ks = 0; ks < 4; ks++) {
                        uint32_t af0[4], af1[4], bf[2];
                        ldm4(af0, abase + SW128(arow * 128 + (ks * 2 + aksel) * 16));
                        ldm4(af1, abase + SW128((16 + arow) * 128 + (ks * 2 + aksel) * 16));
                        ldm2(bf, wbase + SW128((n0 + bnr) * 128 + (ks * 2 + bksel) * 16));
                        mma16816(acc[0], af0, bf);
                        mma16816(acc[1], af1, bf);
                    }
                }
                if (g + 2 < 4) {
                    int gn = g + 2;
                    if (tid < 16) {
                        const int* fp = (const int*)&g_flags[((gn * 16 + tid) * 2 + bs) * 32];
                        int v;
                        do {
                            asm volatile("ld.acquire.gpu.global.b32 %0, [%1];"
                                         : "=r"(v) : "l"(fp));
                        } while (v < t);
                    }
                    __syncthreads();
#pragma unroll
                    for (int cc = 0; cc < 4; cc++) {
                        int c = gn * 4 + cc;
                        cp_async16(Ab + c * 4096 + SW128(srow * 128 + sseg * 16),
                                   hp + (size_t)(bs * 32 + srow) * 2048 + c * 128 + sseg * 16);
                    }
                    cp_commit();
                }
            }
            // gate exchange: Gs[lc][b] (stride 33)
            {
                int bf0 = lane >> 2;
                int lc = n0 + 2 * (lane & 3);
#pragma unroll
                for (int f = 0; f < 2; f++) {
                    int b = f * 16 + bf0;
                    Gs[lc * 33 + b]            = acc[f][0];
                    Gs[(lc + 1) * 33 + b]      = acc[f][1];
                    Gs[lc * 33 + b + 8]        = acc[f][2];
                    Gs[(lc + 1) * 33 + b + 8]  = acc[f][3];
                }
            }
            __syncthreads();
        }

        // ---- cell update: 256 threads x 2 cells ----
        float hv2[2];
#pragma unroll
        for (int e = 0; e < 2; e++) {
            int jl = jl0 + e;
            float i_g = (e ? ggv[0].y : ggv[0].x);
            float f_g = (e ? ggv[1].y : ggv[1].x);
            float g_g = (e ? ggv[2].y : ggv[2].x);
            float o_g = (e ? ggv[3].y : ggv[3].x);
            if (t > 0) {
                i_g += Gs[(0 * 16 + jl) * 33 + bl];
                f_g += Gs[(1 * 16 + jl) * 33 + bl];
                g_g += Gs[(2 * 16 + jl) * 33 + bl];
                o_g += Gs[(3 * 16 + jl) * 33 + bl];
            }
            float cn = sigm(f_g) * creg2[e] + sigm(i_g) * tanh_f(g_g);
            creg2[e] = cn;
            hv2[e] = sigm(o_g) * tanh_f(cn);
        }
        size_t off = (size_t)t * BH + (size_t)(bs * 32 + bl) * 1024 + cg * 16 + jl0;
        *(uint32_t*)(h16 + off) = h2u(__floats2half2_rn(hv2[0], hv2[1]));
        if (yout) {
            *(float2*)(yout + off) = make_float2(hv2[0], hv2[1]);
        }
        if (t == SEQ - 1 && full) {
            size_t tail = (size_t)layer * BH
                        + (size_t)(bs * 32 + bl) * 1024 + cg * 16 + jl0;
            *(float2*)(out + HOFF + tail) = make_float2(hv2[0], hv2[1]);
            *(float2*)(out + COFF + tail) = make_float2(creg2[0], creg2[1]);
        }
        // publish h(t)
        __threadfence();
        __syncthreads();
        if (tid == 0 && t < SEQ - 1)
            asm volatile("st.release.gpu.global.b32 [%0], %1;"
                         :: "l"(&g_flags[jb * 32]), "r"(t + 1) : "memory");
    }
}

// ---------------------------------------------------------------------------
extern "C" void kernel_launch(void* const* d_in, const int* in_sizes, int n_in,
                              void* d_out, int out_size)
{
    const float* x    = (const float*)d_in[0];
    const float* wih0 = (const float*)d_in[1];
    const float* whh0 = (const float*)d_in[2];
    const float* bih0 = (const float*)d_in[3];
    const float* bhh0 = (const float*)d_in[4];
    const float* wih1 = (const float*)d_in[5];
    const float* whh1 = (const float*)d_in[6];
    const float* bih1 = (const float*)d_in[7];
    const float* bhh1 = (const float*)d_in[8];
    float* out = (float*)d_out;

    float *gi; __half *xh, *h16, *wh;
    cudaGetSymbolAddress((void**)&gi,  g_gi);
    cudaGetSymbolAddress((void**)&xh,  g_xh);
    cudaGetSymbolAddress((void**)&h16, g_h16);
    cudaGetSymbolAddress((void**)&wh,  g_wh);

    cudaFuncSetAttribute(gemm_h,  cudaFuncAttributeMaxDynamicSharedMemorySize, GH_SMEM);
    cudaFuncSetAttribute(lstm_df, cudaFuncAttributeMaxDynamicSharedMemorySize, R_SMEM);

    const int full = (out_size >= (int)(YSZ + 4 * BH)) ? 1 : 0;
    dim3 gg(32, 256);
    const int WN8 = G4 * HID / 8;

    f2h_kernel<<<(SEQ * BH / 8 + 255) / 256, 256>>>(x, xh, SEQ * BH / 8);
    f2h_kernel<<<(WN8 + 255) / 256, 256>>>(wih0, wh, WN8);
    f2h_kernel<<<(WN8 + 255) / 256, 256>>>(wih1, wh + (size_t)G4 * HID, WN8);

    // Layer 0
    reset_flags_kernel<<<1, 128>>>();
    gemm_h<<<gg, 256, GH_SMEM>>>(xh, wh, bih0, bhh0, gi);
    lstm_df<<<NCTA, 256, R_SMEM>>>(whh0, gi, h16, (float*)0, out, 0, full);
    // Layer 1 (GEMM A operand = layer-0 h16 stream)
    gemm_h<<<gg, 256, GH_SMEM>>>(h16, wh + (size_t)G4 * HID, bih1, bhh1, gi);
    reset_flags_kernel<<<1, 128>>>();
    lstm_df<<<NCTA, 256, R_SMEM>>>(whh1, gi, h16, out, out, 1, full);
}